// round 10
// baseline (speedup 1.0000x reference)
#include <cuda_runtime.h>
#include <math.h>
#include <stdint.h>

// Problem constants
#define B 4
#define NPTS 8192
#define KNN 20
#define OCH 64
#define EPS 1e-5
#define SLOPE 0.2f
#define INFF __int_as_float(0x7f800000)

// k_knn dynamic smem layout:
//   [0, 128K)        sorted scaled points float4 {-2x,-2y,-2z, sq}
//   [128K, 160K)     packed keys (orig_j << 13) | sorted_pos
//   [160K, 208K)     per-lane queues, depth 24
#define PTS_BYTES (NPTS * 16)
#define KEY_BYTES (NPTS * 4)
#define QDEPTH 24
#define QUEUE_OFF (PTS_BYTES + KEY_BYTES)
#define WQ_BYTES (32 * QDEPTH * 8)            // 6144 per warp
#define SMEM_KNN (QUEUE_OFF + 8 * WQ_BYTES)   // 212992 B = 208 KB

#define SORT_SMEM (NPTS * 8)                  // 64 KB (keys + payload)

// Device scratch (no allocations allowed)
__device__ float4 g_sorted[B * NPTS];
__device__ int    g_skey[B * NPTS];
__device__ int    g_idx[B * NPTS * KNN];
__device__ double g_stats[B * 27];
__device__ float  g_mean[B * OCH];
__device__ float  g_rstd[B * OCH];

// ---------------------------------------------------------------------------
// Kernel 0: zero the moment accumulators (must happen every call)
// ---------------------------------------------------------------------------
__global__ void k_init() {
    int t = threadIdx.x;
    if (t < B * 27) g_stats[t] = 0.0;
}

// ---------------------------------------------------------------------------
// Kernel 1: per-batch bitonic sort of points by x coordinate.
// One block per batch, 512 threads, 64 KB smem. Emits pre-scaled sorted
// points and packed keys (orig_j << 13) | sorted_pos.
// ---------------------------------------------------------------------------
__global__ void k_sort(const float* __restrict__ x) {
    extern __shared__ char sm[];
    float* kx = (float*)sm;
    int*   kj = (int*)(sm + NPTS * 4);
    const int b = blockIdx.x;
    const int tid = threadIdx.x;
    const float* xb = x + b * 3 * NPTS;

    for (int t = tid; t < NPTS; t += blockDim.x) { kx[t] = xb[t]; kj[t] = t; }
    __syncthreads();

    for (int k = 2; k <= NPTS; k <<= 1) {
        for (int j = k >> 1; j > 0; j >>= 1) {
            for (int t = tid; t < NPTS; t += blockDim.x) {
                int ixj = t ^ j;
                if (ixj > t) {
                    bool asc = ((t & k) == 0);
                    float a = kx[t], c2 = kx[ixj];
                    if ((a > c2) == asc) {
                        kx[t] = c2; kx[ixj] = a;
                        int tj = kj[t]; kj[t] = kj[ixj]; kj[ixj] = tj;
                    }
                }
            }
            __syncthreads();
        }
    }

    for (int s = tid; s < NPTS; s += blockDim.x) {
        int oj = kj[s];
        float a0 = xb[oj];
        float a1 = xb[NPTS + oj];
        float a2 = xb[2 * NPTS + oj];
        float sq = fmaf(a0, a0, fmaf(a1, a1, a2 * a2));
        g_sorted[b * NPTS + s] = make_float4(-2.0f * a0, -2.0f * a1, -2.0f * a2, sq);
        g_skey[b * NPTS + s] = (oj << 13) | s;
    }
}

// ---------------------------------------------------------------------------
// Branchless stable LEXICOGRAPHIC insertion into sorted (d, key) list of 20.
// key = (orig_j << 13) | pos, so key order == orig index order: exact jax
// top_k boundary tie semantics (lowest original index kept). Masked callers
// pass (INFF, INT_MAX) -> guaranteed no-op (sd INF slots hold key INT_MAX).
// ---------------------------------------------------------------------------
__device__ __forceinline__ void insert_lex(float (&sd)[KNN], int (&sv)[KNN],
                                           float vd, int vk) {
    bool c[KNN];
#pragma unroll
    for (int k = 0; k < KNN; k++)
        c[k] = (vd < sd[k]) || (vd == sd[k] && vk < sv[k]);
#pragma unroll
    for (int k = KNN - 1; k >= 1; k--) {
        float td = c[k] ? vd : sd[k];
        int   tk = c[k] ? vk : sv[k];
        sd[k] = c[k - 1] ? sd[k - 1] : td;
        sv[k] = c[k - 1] ? sv[k - 1] : tk;
    }
    sd[0] = c[0] ? vd : sd[0];
    sv[0] = c[0] ? vk : sv[0];
}

// ---------------------------------------------------------------------------
// Kernel 2: sorted-sweep exact KNN + fused moment accumulation.
// Block = 256 consecutive sorted queries; full sorted batch staged in smem.
// Warp = 32 consecutive sorted queries: scan own 32 positions, then expand
// left/right in 8-chunks while any lane's x-window test passes (uniform
// branch). d >= dx^2 makes the termination exact; 1e-4 relative margin
// covers fp32 cancellation in the distance formula; stale worst >= final
// worst keeps everything a superset. Queue gate d <= worst is a superset
// too; the lex insert resolves ties exactly.
// ---------------------------------------------------------------------------
__global__ void __launch_bounds__(256) k_knn(const float* __restrict__ x) {
    extern __shared__ char sm[];
    float4* s_pts = (float4*)sm;
    int*    s_key = (int*)(sm + PTS_BYTES);
    __shared__ double sh[27];

    const int b = blockIdx.y;
    const int tid = threadIdx.x;

    const float4* gp = g_sorted + b * NPTS;
    const int*    gk = g_skey + b * NPTS;
    for (int t = tid; t < NPTS; t += 256) {
        s_pts[t] = gp[t];
        s_key[t] = gk[t];
    }
    __syncthreads();

    const int qp = blockIdx.x * 256 + tid;        // sorted query position
    const float4 ps = s_pts[qp];
    const float qx = -0.5f * ps.x, qy = -0.5f * ps.y, qz = -0.5f * ps.z;
    const float qw = ps.w;
    const float myx = qx;                          // raw x of query

    uint32_t sbase;
    asm("{ .reg .u64 t; cvta.to.shared.u64 t, %1; cvt.u32.u64 %0, t; }"
        : "=r"(sbase) : "l"(sm));
    const uint32_t bufA = sbase + (uint32_t)QUEUE_OFF +
                          (uint32_t)(tid >> 5) * (uint32_t)WQ_BYTES +
                          (uint32_t)(tid & 31) * 8u;
    const float2* bufP = (const float2*)(sm + QUEUE_OFF +
                          (tid >> 5) * WQ_BYTES + (tid & 31) * 8);

    float sd[KNN];
    int   sv[KNN];
#pragma unroll
    for (int k = 0; k < KNN; k++) { sd[k] = INFF; sv[k] = 0x7fffffff; }
    float worst = INFF;
    int   cnt = 0;

#define DRAIN() do {                                                   \
        for (int e = 0; __any_sync(0xffffffffu, e < cnt); e++) {       \
            float2 v = bufP[e * 32];                                   \
            bool en = e < cnt;                                         \
            insert_lex(sd, sv, en ? v.x : INFF,                        \
                       en ? __float_as_int(v.y) : 0x7fffffff);         \
        }                                                              \
        worst = sd[KNN - 1];                                           \
        cnt = 0;                                                       \
    } while (0)

#define SCAN8(c0) do {                                                 \
        float dv[8]; int kv[8];                                        \
        _Pragma("unroll")                                              \
        for (int u = 0; u < 8; u++) {                                  \
            float4 p = s_pts[(c0) + u];                                \
            dv[u] = fmaf(qz, p.z, fmaf(qy, p.y, fmaf(qx, p.x, qw + p.w))); \
            kv[u] = s_key[(c0) + u];                                   \
        }                                                              \
        _Pragma("unroll")                                              \
        for (int u = 0; u < 8; u++) {                                  \
            bool t = dv[u] <= worst;                                   \
            uint32_t a = bufA + (uint32_t)cnt * 256u;                  \
            asm volatile(                                              \
                "{ .reg .pred p; setp.ne.u32 p, %0, 0;"                \
                "  @p st.shared.v2.b32 [%1], {%2, %3}; }"              \
                :: "r"((uint32_t)t), "r"(a),                           \
                   "r"(__float_as_int(dv[u])), "r"(kv[u])              \
                : "memory");                                           \
            cnt += t;                                                  \
        }                                                              \
        /* cap: post-check cnt <= 15, +8 -> <= 23 < QDEPTH=24 */       \
        if (__any_sync(0xffffffffu, cnt >= 16)) DRAIN();               \
    } while (0)

    const int warpLo = qp & ~31;

    // phase 1: warp's own 32 sorted positions (includes self, d ~ 0)
    for (int c = warpLo; c < warpLo + 32; c += 8) SCAN8(c);

    // left sweep
    for (int c = warpLo - 8; c >= 0; c -= 8) {
        float xe = -0.5f * s_pts[c + 7].x;     // largest raw x in chunk
        float dxm = myx - xe;                  // >= 0 (sorted)
        bool need = dxm * dxm * 0.9999f < worst;
        if (!__any_sync(0xffffffffu, need)) break;
        SCAN8(c);
    }
    // right sweep
    for (int c = warpLo + 32; c < NPTS; c += 8) {
        float xe = -0.5f * s_pts[c].x;         // smallest raw x in chunk
        float dxm = xe - myx;                  // >= 0 (sorted)
        bool need = dxm * dxm * 0.9999f < worst;
        if (!__any_sync(0xffffffffu, need)) break;
        SCAN8(c);
    }
    DRAIN();
#undef SCAN8
#undef DRAIN

    // write original neighbor indices at the original query's row
    const int origq = s_key[qp] >> 13;
    int* op = g_idx + (b * NPTS + origq) * KNN;
#pragma unroll
    for (int k = 0; k < KNN; k++) op[k] = sv[k] >> 13;

    // ---------------- fused moment accumulation ----------------
    const float nqx = -qx, nqy = -qy, nqz = -qz;
    float sd0 = 0.f, sd1 = 0.f, sd2 = 0.f;
    float s00 = 0.f, s01 = 0.f, s02 = 0.f, s11 = 0.f, s12 = 0.f, s22 = 0.f;
#pragma unroll
    for (int k = 0; k < KNN; k++) {
        float4 p = s_pts[sv[k] & (NPTS - 1)];
        float d0 = fmaf(-0.5f, p.x, nqx);
        float d1 = fmaf(-0.5f, p.y, nqy);
        float d2 = fmaf(-0.5f, p.z, nqz);
        sd0 += d0; sd1 += d1; sd2 += d2;
        s00 = fmaf(d0, d0, s00); s01 = fmaf(d0, d1, s01); s02 = fmaf(d0, d2, s02);
        s11 = fmaf(d1, d1, s11); s12 = fmaf(d1, d2, s12); s22 = fmaf(d2, d2, s22);
    }

    float v[27];
    v[0] = KNN * qx; v[1] = KNN * qy; v[2] = KNN * qz;
    v[3] = sd0; v[4] = sd1; v[5] = sd2;
    v[6] = KNN * qx * qx; v[7] = KNN * qx * qy; v[8]  = KNN * qx * qz;
    v[9] = KNN * qy * qy; v[10] = KNN * qy * qz; v[11] = KNN * qz * qz;
    v[12] = qx * sd0; v[13] = qx * sd1; v[14] = qx * sd2;
    v[15] = qy * sd0; v[16] = qy * sd1; v[17] = qy * sd2;
    v[18] = qz * sd0; v[19] = qz * sd1; v[20] = qz * sd2;
    v[21] = s00; v[22] = s01; v[23] = s02; v[24] = s11; v[25] = s12; v[26] = s22;

#pragma unroll
    for (int q = 0; q < 27; q++) {
#pragma unroll
        for (int off = 16; off > 0; off >>= 1)
            v[q] += __shfl_down_sync(0xffffffffu, v[q], off);
    }

    if (threadIdx.x < 27) sh[threadIdx.x] = 0.0;
    __syncthreads();
    if ((threadIdx.x & 31) == 0) {
#pragma unroll
        for (int q = 0; q < 27; q++) atomicAdd(&sh[q], (double)v[q]);
    }
    __syncthreads();
    if (threadIdx.x < 27) atomicAdd(&g_stats[b * 27 + threadIdx.x], sh[threadIdx.x]);
}

// ---------------------------------------------------------------------------
// Kernel 3: per-(b,o) mean / rstd from the quadratic form.  256 threads.
// ---------------------------------------------------------------------------
__global__ void k_norm(const float* __restrict__ W) {
    int t = threadIdx.x;
    int b = t / OCH, o = t % OCH;
    const float* w = W + o * 6;
    double wa0 = w[0], wa1 = w[1], wa2 = w[2];
    double wb0 = w[3], wb1 = w[4], wb2 = w[5];
    const double* G = g_stats + b * 27;
    const double NK = (double)NPTS * (double)KNN;

    double mean = (wa0 * G[0] + wa1 * G[1] + wa2 * G[2] +
                   wb0 * G[3] + wb1 * G[4] + wb2 * G[5]) / NK;

    double xx = wa0 * wa0 * G[6] + 2.0 * wa0 * wa1 * G[7] + 2.0 * wa0 * wa2 * G[8] +
                wa1 * wa1 * G[9] + 2.0 * wa1 * wa2 * G[10] + wa2 * wa2 * G[11];
    double xd = wa0 * (wb0 * G[12] + wb1 * G[13] + wb2 * G[14]) +
                wa1 * (wb0 * G[15] + wb1 * G[16] + wb2 * G[17]) +
                wa2 * (wb0 * G[18] + wb1 * G[19] + wb2 * G[20]);
    double dd = wb0 * wb0 * G[21] + 2.0 * wb0 * wb1 * G[22] + 2.0 * wb0 * wb2 * G[23] +
                wb1 * wb1 * G[24] + 2.0 * wb1 * wb2 * G[25] + wb2 * wb2 * G[26];

    double Ey2 = (xx + 2.0 * xd + dd) / NK;
    double var = Ey2 - mean * mean;
    g_mean[t] = (float)mean;
    g_rstd[t] = (float)(1.0 / sqrt(var + EPS));
}

// ---------------------------------------------------------------------------
// Kernel 4: conv + max over k (monotone: normalize+leaky applied after max).
// ---------------------------------------------------------------------------
__global__ void k_out(const float* __restrict__ x, const float* __restrict__ W,
                      float* __restrict__ out) {
    const int b = blockIdx.y;
    const int n = blockIdx.x * blockDim.x + threadIdx.x;

    __shared__ float sW[OCH * 6];
    __shared__ float sM[OCH];
    __shared__ float sR[OCH];
    for (int t = threadIdx.x; t < OCH * 6; t += blockDim.x) sW[t] = W[t];
    if (threadIdx.x < OCH) {
        sM[threadIdx.x] = g_mean[b * OCH + threadIdx.x];
        sR[threadIdx.x] = g_rstd[b * OCH + threadIdx.x];
    }
    __syncthreads();

    const float* xb = x + b * 3 * NPTS;
    const float xi0 = xb[n], xi1 = xb[NPTS + n], xi2 = xb[2 * NPTS + n];
    const int* ip = g_idx + (b * NPTS + n) * KNN;

    float d0[KNN], d1[KNN], d2[KNN];
#pragma unroll
    for (int k = 0; k < KNN; k++) {
        int j = ip[k];
        d0[k] = xb[j] - xi0;
        d1[k] = xb[NPTS + j] - xi1;
        d2[k] = xb[2 * NPTS + j] - xi2;
    }

    float* ob = out + (size_t)b * OCH * NPTS + n;
    for (int o = 0; o < OCH; o++) {
        float wa0 = sW[o * 6 + 0], wa1 = sW[o * 6 + 1], wa2 = sW[o * 6 + 2];
        float wb0 = sW[o * 6 + 3], wb1 = sW[o * 6 + 4], wb2 = sW[o * 6 + 5];
        float p = wa0 * xi0;
        p = fmaf(wa1, xi1, p);
        p = fmaf(wa2, xi2, p);
        float m = -3.4e38f;
#pragma unroll
        for (int k = 0; k < KNN; k++) {
            float y = fmaf(wb2, d2[k], fmaf(wb1, d1[k], fmaf(wb0, d0[k], p)));
            m = fmaxf(m, y);
        }
        float z = (m - sM[o]) * sR[o];
        ob[(size_t)o * NPTS] = (z >= 0.f) ? z : SLOPE * z;
    }
}

// ---------------------------------------------------------------------------
extern "C" void kernel_launch(void* const* d_in, const int* in_sizes, int n_in,
                              void* d_out, int out_size) {
    const float* x = (const float*)d_in[0];   // [B, C, N]
    const float* W = (const float*)d_in[1];   // [O, 2C]
    float* out = (float*)d_out;               // [B, O, N]

    cudaFuncSetAttribute(k_sort, cudaFuncAttributeMaxDynamicSharedMemorySize,
                         SORT_SMEM);
    cudaFuncSetAttribute(k_knn, cudaFuncAttributeMaxDynamicSharedMemorySize,
                         SMEM_KNN);

    dim3 grid(NPTS / 256, B);

    k_init<<<1, 128>>>();
    k_sort<<<B, 512, SORT_SMEM>>>(x);
    k_knn<<<grid, 256, SMEM_KNN>>>(x);
    k_norm<<<1, B * OCH>>>(W);
    k_out<<<grid, 256>>>(x, W, out);
}

// round 11
// speedup vs baseline: 1.2121x; 1.2121x over previous
#include <cuda_runtime.h>
#include <math.h>
#include <stdint.h>

// Problem constants
#define B 4
#define NPTS 8192
#define KNN 20
#define OCH 64
#define EPS 1e-5
#define SLOPE 0.2f
#define INFF __int_as_float(0x7f800000)

// k_knn dynamic smem layout:
//   [0, 128K)        sorted scaled points float4 {-2x,-2y,-2z, sq}
//   [128K, 160K)     packed keys (orig_j << 13) | sorted_pos
//   [160K, 208K)     per-lane queues, depth 24
#define PTS_BYTES (NPTS * 16)
#define KEY_BYTES (NPTS * 4)
#define QDEPTH 24
#define QUEUE_OFF (PTS_BYTES + KEY_BYTES)
#define WQ_BYTES (32 * QDEPTH * 8)            // 6144 per warp
#define SMEM_KNN (QUEUE_OFF + 8 * WQ_BYTES)   // 208 KB

// k_bin dynamic smem layout
#define NBIN 1024
#define SX_OFF   0                            // float[8192]  32 KB
#define SJ_OFF   (NPTS * 4)                   // int[8192]    32 KB
#define HIST_OFF (SJ_OFF + NPTS * 4)          // int[1024]     4 KB
#define PREF_OFF (HIST_OFF + NBIN * 4)        // int[1024]     4 KB
#define OFS_OFF  (PREF_OFF + NBIN * 4)        // int[1024]     4 KB
#define RED_OFF  (OFS_OFF + NBIN * 4)         // float[34]
#define BIN_SMEM (RED_OFF + 64 * 4)

// Device scratch (no allocations allowed)
__device__ float4 g_sorted[B * NPTS];
__device__ int    g_skey[B * NPTS];
__device__ int    g_idx[B * NPTS * KNN];
__device__ double g_stats[B * 27];
__device__ float  g_mean[B * OCH];
__device__ float  g_rstd[B * OCH];

// ---------------------------------------------------------------------------
// Kernel 0: zero the moment accumulators (must happen every call)
// ---------------------------------------------------------------------------
__global__ void k_init() {
    int t = threadIdx.x;
    if (t < B * 27) g_stats[t] = 0.0;
}

// ---------------------------------------------------------------------------
// Kernel 1: per-batch O(N) x-sort: uniform 1024-bin bucket scatter + per-bin
// insertion sort (avg 8/bin, peak ~25 for Gaussian x). One block per batch.
// Emits pre-scaled sorted points and packed keys (orig_j << 13) | sorted_pos.
// ---------------------------------------------------------------------------
__global__ void k_bin(const float* __restrict__ x) {
    extern __shared__ char sm[];
    float* sx   = (float*)(sm + SX_OFF);
    int*   sj   = (int*)(sm + SJ_OFF);
    int*   hist = (int*)(sm + HIST_OFF);
    int*   pref = (int*)(sm + PREF_OFF);
    int*   ofs  = (int*)(sm + OFS_OFF);
    float* red  = (float*)(sm + RED_OFF);

    const int b = blockIdx.x;
    const int tid = threadIdx.x;
    const float* xb = x + b * 3 * NPTS;

    // ---- block min/max of x ----
    float lmin = 3.4e38f, lmax = -3.4e38f;
    for (int t = tid; t < NPTS; t += 512) {
        float v = xb[t];
        lmin = fminf(lmin, v);
        lmax = fmaxf(lmax, v);
    }
#pragma unroll
    for (int o = 16; o > 0; o >>= 1) {
        lmin = fminf(lmin, __shfl_down_sync(0xffffffffu, lmin, o));
        lmax = fmaxf(lmax, __shfl_down_sync(0xffffffffu, lmax, o));
    }
    if ((tid & 31) == 0) { red[tid >> 5] = lmin; red[16 + (tid >> 5)] = lmax; }
    __syncthreads();
    if (tid == 0) {
        float m0 = red[0], m1 = red[16];
        for (int w = 1; w < 16; w++) {
            m0 = fminf(m0, red[w]);
            m1 = fmaxf(m1, red[16 + w]);
        }
        red[32] = m0; red[33] = m1;
    }
    // zero histogram
    hist[tid] = 0; hist[tid + 512] = 0;
    __syncthreads();
    const float bmin = red[32], bmax = red[33];
    const float inv = (float)NBIN / (bmax - bmin);

    // ---- histogram ----
    for (int t = tid; t < NPTS; t += 512) {
        int idx = min(NBIN - 1, (int)((xb[t] - bmin) * inv));
        atomicAdd(&hist[idx], 1);
    }
    __syncthreads();

    // ---- exclusive prefix (warp 0, chunked shfl scan) ----
    if (tid < 32) {
        int csum = 0;
        for (int q = 0; q < 32; q++) csum += hist[tid * 32 + q];
        int run = csum;
#pragma unroll
        for (int o = 1; o < 32; o <<= 1) {
            int v = __shfl_up_sync(0xffffffffu, run, o);
            if (tid >= o) run += v;
        }
        int acc = run - csum;   // exclusive chunk base
        for (int q = 0; q < 32; q++) {
            pref[tid * 32 + q] = acc;
            acc += hist[tid * 32 + q];
        }
    }
    __syncthreads();
    ofs[tid] = pref[tid]; ofs[tid + 512] = pref[tid + 512];
    __syncthreads();

    // ---- scatter (x, orig j) into bin-grouped smem ----
    for (int t = tid; t < NPTS; t += 512) {
        float v = xb[t];
        int idx = min(NBIN - 1, (int)((v - bmin) * inv));
        int p = atomicAdd(&ofs[idx], 1);
        sx[p] = v; sj[p] = t;
    }
    __syncthreads();

    // ---- per-bin insertion sort (each thread: bins tid and tid+512) ----
#pragma unroll
    for (int h = 0; h < 2; h++) {
        int bin = tid + h * 512;
        int s0 = pref[bin], s1 = s0 + hist[bin];
        for (int a = s0 + 1; a < s1; a++) {
            float kv = sx[a]; int jv = sj[a];
            int c = a - 1;
            while (c >= s0 && sx[c] > kv) {
                sx[c + 1] = sx[c]; sj[c + 1] = sj[c];
                c--;
            }
            sx[c + 1] = kv; sj[c + 1] = jv;
        }
    }
    __syncthreads();

    // ---- emit sorted scaled points + packed keys ----
    for (int s = tid; s < NPTS; s += 512) {
        int oj = sj[s];
        float a0 = sx[s];
        float a1 = xb[NPTS + oj];
        float a2 = xb[2 * NPTS + oj];
        float sq = fmaf(a0, a0, fmaf(a1, a1, a2 * a2));
        g_sorted[b * NPTS + s] = make_float4(-2.0f * a0, -2.0f * a1, -2.0f * a2, sq);
        g_skey[b * NPTS + s] = (oj << 13) | s;
    }
}

// ---------------------------------------------------------------------------
// Branchless stable LEXICOGRAPHIC insertion into sorted (d, key) list of 20.
// key = (orig_j << 13) | pos, so key order == orig index order: exact jax
// top_k boundary tie semantics. Masked callers pass (INFF, INT_MAX) -> no-op.
// ---------------------------------------------------------------------------
__device__ __forceinline__ void insert_lex(float (&sd)[KNN], int (&sv)[KNN],
                                           float vd, int vk) {
    bool c[KNN];
#pragma unroll
    for (int k = 0; k < KNN; k++)
        c[k] = (vd < sd[k]) || (vd == sd[k] && vk < sv[k]);
#pragma unroll
    for (int k = KNN - 1; k >= 1; k--) {
        float td = c[k] ? vd : sd[k];
        int   tk = c[k] ? vk : sv[k];
        sd[k] = c[k - 1] ? sd[k - 1] : td;
        sv[k] = c[k - 1] ? sv[k - 1] : tk;
    }
    sd[0] = c[0] ? vd : sd[0];
    sv[0] = c[0] ? vk : sv[0];
}

// ---------------------------------------------------------------------------
// Kernel 2: sorted-sweep exact KNN + fused moment accumulation (validated in
// R10). Warp = 32 consecutive sorted queries: scan own 32, then expand
// left/right in 8-chunks while any lane's x-window test passes (uniform
// branch). d >= dx^2 makes termination exact; 1e-4 relative margin covers
// fp32 cancellation; stale worst >= final worst keeps supersets. Queue gate
// d <= worst is a superset; lex insert resolves ties exactly.
// ---------------------------------------------------------------------------
__global__ void __launch_bounds__(256) k_knn(const float* __restrict__ x) {
    extern __shared__ char sm[];
    float4* s_pts = (float4*)sm;
    int*    s_key = (int*)(sm + PTS_BYTES);
    __shared__ double sh[27];

    const int b = blockIdx.y;
    const int tid = threadIdx.x;

    const float4* gp = g_sorted + b * NPTS;
    const int*    gk = g_skey + b * NPTS;
    for (int t = tid; t < NPTS; t += 256) {
        s_pts[t] = gp[t];
        s_key[t] = gk[t];
    }
    __syncthreads();

    const int qp = blockIdx.x * 256 + tid;        // sorted query position
    const float4 ps = s_pts[qp];
    const float qx = -0.5f * ps.x, qy = -0.5f * ps.y, qz = -0.5f * ps.z;
    const float qw = ps.w;
    const float myx = qx;                          // raw x of query

    uint32_t sbase;
    asm("{ .reg .u64 t; cvta.to.shared.u64 t, %1; cvt.u32.u64 %0, t; }"
        : "=r"(sbase) : "l"(sm));
    const uint32_t bufA = sbase + (uint32_t)QUEUE_OFF +
                          (uint32_t)(tid >> 5) * (uint32_t)WQ_BYTES +
                          (uint32_t)(tid & 31) * 8u;
    const float2* bufP = (const float2*)(sm + QUEUE_OFF +
                          (tid >> 5) * WQ_BYTES + (tid & 31) * 8);

    float sd[KNN];
    int   sv[KNN];
#pragma unroll
    for (int k = 0; k < KNN; k++) { sd[k] = INFF; sv[k] = 0x7fffffff; }
    float worst = INFF;
    int   cnt = 0;

#define DRAIN() do {                                                   \
        for (int e = 0; __any_sync(0xffffffffu, e < cnt); e++) {       \
            float2 v = bufP[e * 32];                                   \
            bool en = e < cnt;                                         \
            insert_lex(sd, sv, en ? v.x : INFF,                        \
                       en ? __float_as_int(v.y) : 0x7fffffff);         \
        }                                                              \
        worst = sd[KNN - 1];                                           \
        cnt = 0;                                                       \
    } while (0)

#define SCAN8(c0) do {                                                 \
        float dv[8]; int kv[8];                                        \
        _Pragma("unroll")                                              \
        for (int u = 0; u < 8; u++) {                                  \
            float4 p = s_pts[(c0) + u];                                \
            dv[u] = fmaf(qz, p.z, fmaf(qy, p.y, fmaf(qx, p.x, qw + p.w))); \
            kv[u] = s_key[(c0) + u];                                   \
        }                                                              \
        _Pragma("unroll")                                              \
        for (int u = 0; u < 8; u++) {                                  \
            bool t = dv[u] <= worst;                                   \
            uint32_t a = bufA + (uint32_t)cnt * 256u;                  \
            asm volatile(                                              \
                "{ .reg .pred p; setp.ne.u32 p, %0, 0;"                \
                "  @p st.shared.v2.b32 [%1], {%2, %3}; }"              \
                :: "r"((uint32_t)t), "r"(a),                           \
                   "r"(__float_as_int(dv[u])), "r"(kv[u])              \
                : "memory");                                           \
            cnt += t;                                                  \
        }                                                              \
        /* cap: post-check cnt <= 15, +8 -> <= 23 < QDEPTH=24 */       \
        if (__any_sync(0xffffffffu, cnt >= 16)) DRAIN();               \
    } while (0)

    const int warpLo = qp & ~31;

    // phase 1: warp's own 32 sorted positions (includes self, d ~ 0)
    for (int c = warpLo; c < warpLo + 32; c += 8) SCAN8(c);

    // left sweep
    for (int c = warpLo - 8; c >= 0; c -= 8) {
        float xe = -0.5f * s_pts[c + 7].x;     // largest raw x in chunk
        float dxm = myx - xe;                  // >= 0 (sorted)
        bool need = dxm * dxm * 0.9999f < worst;
        if (!__any_sync(0xffffffffu, need)) break;
        SCAN8(c);
    }
    // right sweep
    for (int c = warpLo + 32; c < NPTS; c += 8) {
        float xe = -0.5f * s_pts[c].x;         // smallest raw x in chunk
        float dxm = xe - myx;                  // >= 0 (sorted)
        bool need = dxm * dxm * 0.9999f < worst;
        if (!__any_sync(0xffffffffu, need)) break;
        SCAN8(c);
    }
    DRAIN();
#undef SCAN8
#undef DRAIN

    // write original neighbor indices at the original query's row
    const int origq = s_key[qp] >> 13;
    int* op = g_idx + (b * NPTS + origq) * KNN;
#pragma unroll
    for (int k = 0; k < KNN; k++) op[k] = sv[k] >> 13;

    // ---------------- fused moment accumulation ----------------
    const float nqx = -qx, nqy = -qy, nqz = -qz;
    float sd0 = 0.f, sd1 = 0.f, sd2 = 0.f;
    float s00 = 0.f, s01 = 0.f, s02 = 0.f, s11 = 0.f, s12 = 0.f, s22 = 0.f;
#pragma unroll
    for (int k = 0; k < KNN; k++) {
        float4 p = s_pts[sv[k] & (NPTS - 1)];
        float d0 = fmaf(-0.5f, p.x, nqx);
        float d1 = fmaf(-0.5f, p.y, nqy);
        float d2 = fmaf(-0.5f, p.z, nqz);
        sd0 += d0; sd1 += d1; sd2 += d2;
        s00 = fmaf(d0, d0, s00); s01 = fmaf(d0, d1, s01); s02 = fmaf(d0, d2, s02);
        s11 = fmaf(d1, d1, s11); s12 = fmaf(d1, d2, s12); s22 = fmaf(d2, d2, s22);
    }

    float v[27];
    v[0] = KNN * qx; v[1] = KNN * qy; v[2] = KNN * qz;
    v[3] = sd0; v[4] = sd1; v[5] = sd2;
    v[6] = KNN * qx * qx; v[7] = KNN * qx * qy; v[8]  = KNN * qx * qz;
    v[9] = KNN * qy * qy; v[10] = KNN * qy * qz; v[11] = KNN * qz * qz;
    v[12] = qx * sd0; v[13] = qx * sd1; v[14] = qx * sd2;
    v[15] = qy * sd0; v[16] = qy * sd1; v[17] = qy * sd2;
    v[18] = qz * sd0; v[19] = qz * sd1; v[20] = qz * sd2;
    v[21] = s00; v[22] = s01; v[23] = s02; v[24] = s11; v[25] = s12; v[26] = s22;

#pragma unroll
    for (int q = 0; q < 27; q++) {
#pragma unroll
        for (int off = 16; off > 0; off >>= 1)
            v[q] += __shfl_down_sync(0xffffffffu, v[q], off);
    }

    if (threadIdx.x < 27) sh[threadIdx.x] = 0.0;
    __syncthreads();
    if ((threadIdx.x & 31) == 0) {
#pragma unroll
        for (int q = 0; q < 27; q++) atomicAdd(&sh[q], (double)v[q]);
    }
    __syncthreads();
    if (threadIdx.x < 27) atomicAdd(&g_stats[b * 27 + threadIdx.x], sh[threadIdx.x]);
}

// ---------------------------------------------------------------------------
// Kernel 3: per-(b,o) mean / rstd from the quadratic form.  256 threads.
// ---------------------------------------------------------------------------
__global__ void k_norm(const float* __restrict__ W) {
    int t = threadIdx.x;
    int b = t / OCH, o = t % OCH;
    const float* w = W + o * 6;
    double wa0 = w[0], wa1 = w[1], wa2 = w[2];
    double wb0 = w[3], wb1 = w[4], wb2 = w[5];
    const double* G = g_stats + b * 27;
    const double NK = (double)NPTS * (double)KNN;

    double mean = (wa0 * G[0] + wa1 * G[1] + wa2 * G[2] +
                   wb0 * G[3] + wb1 * G[4] + wb2 * G[5]) / NK;

    double xx = wa0 * wa0 * G[6] + 2.0 * wa0 * wa1 * G[7] + 2.0 * wa0 * wa2 * G[8] +
                wa1 * wa1 * G[9] + 2.0 * wa1 * wa2 * G[10] + wa2 * wa2 * G[11];
    double xd = wa0 * (wb0 * G[12] + wb1 * G[13] + wb2 * G[14]) +
                wa1 * (wb0 * G[15] + wb1 * G[16] + wb2 * G[17]) +
                wa2 * (wb0 * G[18] + wb1 * G[19] + wb2 * G[20]);
    double dd = wb0 * wb0 * G[21] + 2.0 * wb0 * wb1 * G[22] + 2.0 * wb0 * wb2 * G[23] +
                wb1 * wb1 * G[24] + 2.0 * wb1 * wb2 * G[25] + wb2 * wb2 * G[26];

    double Ey2 = (xx + 2.0 * xd + dd) / NK;
    double var = Ey2 - mean * mean;
    g_mean[t] = (float)mean;
    g_rstd[t] = (float)(1.0 / sqrt(var + EPS));
}

// ---------------------------------------------------------------------------
// Kernel 4: conv + max over k (monotone: normalize+leaky applied after max).
// ---------------------------------------------------------------------------
__global__ void k_out(const float* __restrict__ x, const float* __restrict__ W,
                      float* __restrict__ out) {
    const int b = blockIdx.y;
    const int n = blockIdx.x * blockDim.x + threadIdx.x;

    __shared__ float sW[OCH * 6];
    __shared__ float sM[OCH];
    __shared__ float sR[OCH];
    for (int t = threadIdx.x; t < OCH * 6; t += blockDim.x) sW[t] = W[t];
    if (threadIdx.x < OCH) {
        sM[threadIdx.x] = g_mean[b * OCH + threadIdx.x];
        sR[threadIdx.x] = g_rstd[b * OCH + threadIdx.x];
    }
    __syncthreads();

    const float* xb = x + b * 3 * NPTS;
    const float xi0 = xb[n], xi1 = xb[NPTS + n], xi2 = xb[2 * NPTS + n];
    const int* ip = g_idx + (b * NPTS + n) * KNN;

    float d0[KNN], d1[KNN], d2[KNN];
#pragma unroll
    for (int k = 0; k < KNN; k++) {
        int j = ip[k];
        d0[k] = xb[j] - xi0;
        d1[k] = xb[NPTS + j] - xi1;
        d2[k] = xb[2 * NPTS + j] - xi2;
    }

    float* ob = out + (size_t)b * OCH * NPTS + n;
    for (int o = 0; o < OCH; o++) {
        float wa0 = sW[o * 6 + 0], wa1 = sW[o * 6 + 1], wa2 = sW[o * 6 + 2];
        float wb0 = sW[o * 6 + 3], wb1 = sW[o * 6 + 4], wb2 = sW[o * 6 + 5];
        float p = wa0 * xi0;
        p = fmaf(wa1, xi1, p);
        p = fmaf(wa2, xi2, p);
        float m = -3.4e38f;
#pragma unroll
        for (int k = 0; k < KNN; k++) {
            float y = fmaf(wb2, d2[k], fmaf(wb1, d1[k], fmaf(wb0, d0[k], p)));
            m = fmaxf(m, y);
        }
        float z = (m - sM[o]) * sR[o];
        ob[(size_t)o * NPTS] = (z >= 0.f) ? z : SLOPE * z;
    }
}

// ---------------------------------------------------------------------------
extern "C" void kernel_launch(void* const* d_in, const int* in_sizes, int n_in,
                              void* d_out, int out_size) {
    const float* x = (const float*)d_in[0];   // [B, C, N]
    const float* W = (const float*)d_in[1];   // [O, 2C]
    float* out = (float*)d_out;               // [B, O, N]

    cudaFuncSetAttribute(k_bin, cudaFuncAttributeMaxDynamicSharedMemorySize,
                         BIN_SMEM);
    cudaFuncSetAttribute(k_knn, cudaFuncAttributeMaxDynamicSharedMemorySize,
                         SMEM_KNN);

    dim3 grid(NPTS / 256, B);

    k_init<<<1, 128>>>();
    k_bin<<<B, 512, BIN_SMEM>>>(x);
    k_knn<<<grid, 256, SMEM_KNN>>>(x);
    k_norm<<<1, B * OCH>>>(W);
    k_out<<<grid, 256>>>(x, W, out);
}

// round 12
// speedup vs baseline: 2.6447x; 2.1820x over previous
#include <cuda_runtime.h>
#include <math.h>
#include <stdint.h>

// Problem constants
#define B 4
#define NPTS 8192
#define KNN 20
#define OCH 64
#define EPS 1e-5
#define SLOPE 0.2f
#define INFF __int_as_float(0x7f800000)

// dynamic smem layout: [0,128K) staged points, then per-lane queues depth 48
#define PTS_BYTES (NPTS * 16)
#define QDEPTH 48
#define WQ_BYTES (32 * QDEPTH * 8)            // 12288 per warp
#define SMEM_TOTAL (PTS_BYTES + 8 * WQ_BYTES) // 224 KB

// Device scratch (no allocations allowed)
__device__ int    g_idx[B * NPTS * KNN];
__device__ double g_stats[B * 27];
__device__ float  g_mean[B * OCH];
__device__ float  g_rstd[B * OCH];

// ---------------------------------------------------------------------------
// Kernel 0: zero the moment accumulators (must happen every call)
// ---------------------------------------------------------------------------
__global__ void k_init() {
    int t = threadIdx.x;
    if (t < B * 27) g_stats[t] = 0.0;
}

// ---------------------------------------------------------------------------
// Branchless stable insertion into sorted-ascending (d, j) list of 20.
// Upper-bound placement (strict <): incoming value lands AFTER existing
// equal-d entries. Candidates arrive in ascending j (queue preserves push
// order), so ties are ordered by ascending j; evicted worst is the
// lexicographically largest (d, j) == jax top_k boundary semantics.
// Idempotent for vd = +INF.
// ---------------------------------------------------------------------------
__device__ __forceinline__ void insert_dj(float (&sd)[KNN], int (&sj)[KNN],
                                          float vd, int vj) {
    bool c[KNN];
#pragma unroll
    for (int k = 0; k < KNN; k++) c[k] = vd < sd[k];
#pragma unroll
    for (int k = KNN - 1; k >= 1; k--) {
        float td = c[k] ? vd : sd[k];
        int   tj = c[k] ? vj : sj[k];
        sd[k] = c[k - 1] ? sd[k - 1] : td;
        sj[k] = c[k - 1] ? sj[k - 1] : tj;
    }
    sd[0] = c[0] ? vd : sd[0];
    sj[0] = c[0] ? vj : sj[0];
}

// ---------------------------------------------------------------------------
// Kernel 1: flat exact KNN + fused moment accumulation (validated R7
// structure, tightened). Distances carry a per-query monotone shift (-|q|^2
// folded out): ordering and tie structure within a query are preserved, and
// only the selected index SET feeds downstream. Hot loop per 32-point group:
// PHASE 1 pure LDS+math (batched LDS.128), PHASE 2 single fused PTX block
// per point (setp.lt + @p store + @p count) -> no BSSY, 3 instr/pt.
// One uniform drain-check branch per group.
// ---------------------------------------------------------------------------
__global__ void __launch_bounds__(256) k_knn(const float* __restrict__ x) {
    extern __shared__ char sm[];
    float4* s_pts = (float4*)sm;
    __shared__ double sh[27];

    const int b = blockIdx.y;
    const float* xb = x + b * 3 * NPTS;

    // stage points scaled {-2x,-2y,-2z, ||x||^2}
    for (int j = threadIdx.x; j < NPTS; j += blockDim.x) {
        float a0 = xb[j];
        float a1 = xb[NPTS + j];
        float a2 = xb[2 * NPTS + j];
        float sq = fmaf(a0, a0, fmaf(a1, a1, a2 * a2));
        s_pts[j] = make_float4(-2.0f * a0, -2.0f * a1, -2.0f * a2, sq);
    }
    __syncthreads();

    const int tid = threadIdx.x;
    const int i = blockIdx.x * blockDim.x + tid;
    const float4 ps = s_pts[i];
    const float qx = -0.5f * ps.x, qy = -0.5f * ps.y, qz = -0.5f * ps.z;

    // lane-private queue: entry e at byte offset e*256 from bufA
    uint32_t sbase;
    asm("{ .reg .u64 t; cvta.to.shared.u64 t, %1; cvt.u32.u64 %0, t; }"
        : "=r"(sbase) : "l"(sm));
    const uint32_t bufA = sbase + (uint32_t)PTS_BYTES +
                          (uint32_t)(tid >> 5) * (uint32_t)WQ_BYTES +
                          (uint32_t)(tid & 31) * 8u;
    const float2* bufP = (const float2*)(sm + PTS_BYTES +
                          (tid >> 5) * WQ_BYTES + (tid & 31) * 8);

    float sd[KNN];
    int   sj[KNN];
#pragma unroll
    for (int k = 0; k < KNN; k++) { sd[k] = INFF; sj[k] = 0; }
    float worst = INFF;   // stays INF until list holds 20 real entries
    int   cnt = 0;

#define DRAIN() do {                                                   \
        for (int e = 0; __any_sync(0xffffffffu, e < cnt); e++) {       \
            float2 v = bufP[e * 32];                                   \
            float vd = (e < cnt) ? v.x : INFF;                         \
            insert_dj(sd, sj, vd, __float_as_int(v.y));                \
        }                                                              \
        worst = sd[KNN - 1];                                           \
        cnt = 0;                                                       \
    } while (0)

    for (int j0 = 0; j0 < NPTS; j0 += 32) {
        // PHASE 1: pure loads + math (no asm in scope -> batched LDS.128).
        // shifted distance d' = d - |q|^2  (monotone per query)
        float dv[32];
#pragma unroll
        for (int u = 0; u < 32; u++) {
            float4 p = s_pts[j0 + u];
            dv[u] = fmaf(qz, p.z, fmaf(qy, p.y, fmaf(qx, p.x, p.w)));
        }
        // PHASE 2: fused gate + predicated queue store + count (branch-free)
#pragma unroll
        for (int u = 0; u < 32; u++) {
            uint32_t a = bufA + (uint32_t)cnt * 256u;
            asm volatile(
                "{ .reg .pred p; setp.lt.f32 p, %2, %3;"
                "  @p st.shared.v2.b32 [%1], {%4, %5};"
                "  @p add.u32 %0, %0, 1; }"
                : "+r"(cnt)
                : "r"(a), "f"(dv[u]), "f"(worst),
                  "r"(__float_as_int(dv[u])), "r"(j0 + u)
                : "memory");
        }
        // cap proof: post-check cnt <= 15, +32 -> <= 47 < QDEPTH=48
        if (__any_sync(0xffffffffu, cnt >= 16)) DRAIN();
    }
    DRAIN();   // leftovers
#undef DRAIN

    int* op = g_idx + (b * NPTS + i) * KNN;
#pragma unroll
    for (int k = 0; k < KNN; k++) op[k] = sj[k];

    // ---------------- fused moment accumulation ----------------
    // deltas: xj - xi = (-0.5*p.x) - qx  (exact power-of-two rescale)
    const float nqx = -qx, nqy = -qy, nqz = -qz;
    float sd0 = 0.f, sd1 = 0.f, sd2 = 0.f;
    float s00 = 0.f, s01 = 0.f, s02 = 0.f, s11 = 0.f, s12 = 0.f, s22 = 0.f;
#pragma unroll
    for (int k = 0; k < KNN; k++) {
        float4 p = s_pts[sj[k]];
        float d0 = fmaf(-0.5f, p.x, nqx);
        float d1 = fmaf(-0.5f, p.y, nqy);
        float d2 = fmaf(-0.5f, p.z, nqz);
        sd0 += d0; sd1 += d1; sd2 += d2;
        s00 = fmaf(d0, d0, s00); s01 = fmaf(d0, d1, s01); s02 = fmaf(d0, d2, s02);
        s11 = fmaf(d1, d1, s11); s12 = fmaf(d1, d2, s12); s22 = fmaf(d2, d2, s22);
    }

    float v[27];
    v[0] = KNN * qx; v[1] = KNN * qy; v[2] = KNN * qz;
    v[3] = sd0; v[4] = sd1; v[5] = sd2;
    v[6] = KNN * qx * qx; v[7] = KNN * qx * qy; v[8]  = KNN * qx * qz;
    v[9] = KNN * qy * qy; v[10] = KNN * qy * qz; v[11] = KNN * qz * qz;
    v[12] = qx * sd0; v[13] = qx * sd1; v[14] = qx * sd2;
    v[15] = qy * sd0; v[16] = qy * sd1; v[17] = qy * sd2;
    v[18] = qz * sd0; v[19] = qz * sd1; v[20] = qz * sd2;
    v[21] = s00; v[22] = s01; v[23] = s02; v[24] = s11; v[25] = s12; v[26] = s22;

#pragma unroll
    for (int q = 0; q < 27; q++) {
#pragma unroll
        for (int off = 16; off > 0; off >>= 1)
            v[q] += __shfl_down_sync(0xffffffffu, v[q], off);
    }

    if (threadIdx.x < 27) sh[threadIdx.x] = 0.0;
    __syncthreads();
    if ((threadIdx.x & 31) == 0) {
#pragma unroll
        for (int q = 0; q < 27; q++) atomicAdd(&sh[q], (double)v[q]);
    }
    __syncthreads();
    if (threadIdx.x < 27) atomicAdd(&g_stats[b * 27 + threadIdx.x], sh[threadIdx.x]);
}

// ---------------------------------------------------------------------------
// Kernel 2: per-(b,o) mean / rstd from the quadratic form.  256 threads.
// ---------------------------------------------------------------------------
__global__ void k_norm(const float* __restrict__ W) {
    int t = threadIdx.x;
    int b = t / OCH, o = t % OCH;
    const float* w = W + o * 6;
    double wa0 = w[0], wa1 = w[1], wa2 = w[2];
    double wb0 = w[3], wb1 = w[4], wb2 = w[5];
    const double* G = g_stats + b * 27;
    const double NK = (double)NPTS * (double)KNN;

    double mean = (wa0 * G[0] + wa1 * G[1] + wa2 * G[2] +
                   wb0 * G[3] + wb1 * G[4] + wb2 * G[5]) / NK;

    double xx = wa0 * wa0 * G[6] + 2.0 * wa0 * wa1 * G[7] + 2.0 * wa0 * wa2 * G[8] +
                wa1 * wa1 * G[9] + 2.0 * wa1 * wa2 * G[10] + wa2 * wa2 * G[11];
    double xd = wa0 * (wb0 * G[12] + wb1 * G[13] + wb2 * G[14]) +
                wa1 * (wb0 * G[15] + wb1 * G[16] + wb2 * G[17]) +
                wa2 * (wb0 * G[18] + wb1 * G[19] + wb2 * G[20]);
    double dd = wb0 * wb0 * G[21] + 2.0 * wb0 * wb1 * G[22] + 2.0 * wb0 * wb2 * G[23] +
                wb1 * wb1 * G[24] + 2.0 * wb1 * wb2 * G[25] + wb2 * wb2 * G[26];

    double Ey2 = (xx + 2.0 * xd + dd) / NK;
    double var = Ey2 - mean * mean;
    g_mean[t] = (float)mean;
    g_rstd[t] = (float)(1.0 / sqrt(var + EPS));
}

// ---------------------------------------------------------------------------
// Kernel 3: conv + max over k (monotone: normalize+leaky applied after max).
// ---------------------------------------------------------------------------
__global__ void k_out(const float* __restrict__ x, const float* __restrict__ W,
                      float* __restrict__ out) {
    const int b = blockIdx.y;
    const int n = blockIdx.x * blockDim.x + threadIdx.x;

    __shared__ float sW[OCH * 6];
    __shared__ float sM[OCH];
    __shared__ float sR[OCH];
    for (int t = threadIdx.x; t < OCH * 6; t += blockDim.x) sW[t] = W[t];
    if (threadIdx.x < OCH) {
        sM[threadIdx.x] = g_mean[b * OCH + threadIdx.x];
        sR[threadIdx.x] = g_rstd[b * OCH + threadIdx.x];
    }
    __syncthreads();

    const float* xb = x + b * 3 * NPTS;
    const float xi0 = xb[n], xi1 = xb[NPTS + n], xi2 = xb[2 * NPTS + n];
    const int* ip = g_idx + (b * NPTS + n) * KNN;

    float d0[KNN], d1[KNN], d2[KNN];
#pragma unroll
    for (int k = 0; k < KNN; k++) {
        int j = ip[k];
        d0[k] = xb[j] - xi0;
        d1[k] = xb[NPTS + j] - xi1;
        d2[k] = xb[2 * NPTS + j] - xi2;
    }

    float* ob = out + (size_t)b * OCH * NPTS + n;
    for (int o = 0; o < OCH; o++) {
        float wa0 = sW[o * 6 + 0], wa1 = sW[o * 6 + 1], wa2 = sW[o * 6 + 2];
        float wb0 = sW[o * 6 + 3], wb1 = sW[o * 6 + 4], wb2 = sW[o * 6 + 5];
        float p = wa0 * xi0;
        p = fmaf(wa1, xi1, p);
        p = fmaf(wa2, xi2, p);
        float m = -3.4e38f;
#pragma unroll
        for (int k = 0; k < KNN; k++) {
            float y = fmaf(wb2, d2[k], fmaf(wb1, d1[k], fmaf(wb0, d0[k], p)));
            m = fmaxf(m, y);
        }
        float z = (m - sM[o]) * sR[o];
        ob[(size_t)o * NPTS] = (z >= 0.f) ? z : SLOPE * z;
    }
}

// ---------------------------------------------------------------------------
extern "C" void kernel_launch(void* const* d_in, const int* in_sizes, int n_in,
                              void* d_out, int out_size) {
    const float* x = (const float*)d_in[0];   // [B, C, N]
    const float* W = (const float*)d_in[1];   // [O, 2C]
    float* out = (float*)d_out;               // [B, O, N]

    cudaFuncSetAttribute(k_knn, cudaFuncAttributeMaxDynamicSharedMemorySize,
                         SMEM_TOTAL);

    dim3 grid(NPTS / 256, B);

    k_init<<<1, 128>>>();
    k_knn<<<grid, 256, SMEM_TOTAL>>>(x);
    k_norm<<<1, B * OCH>>>(W);
    k_out<<<grid, 256>>>(x, W, out);
}

// round 13
// speedup vs baseline: 2.6947x; 1.0189x over previous
#include <cuda_runtime.h>
#include <math.h>
#include <stdint.h>

// Problem constants
#define B 4
#define NPTS 8192
#define KNN 20
#define OCH 64
#define EPS 1e-5
#define SLOPE 0.2f
#define INFF __int_as_float(0x7f800000)

// k_knn grid: 37 blocks x 224 threads per batch = 8288 slots (96 masked)
#define KBLK 37
#define KTHR 224
#define KWARPS 7

// dynamic smem: [0,128K) staged points, then 7 per-warp lane queues depth 48
#define PTS_BYTES (NPTS * 16)
#define QDEPTH 48
#define WQ_BYTES (32 * QDEPTH * 8)                  // 12288 per warp
#define SMEM_TOTAL (PTS_BYTES + KWARPS * WQ_BYTES)  // 217088 B

// Device scratch (no allocations allowed)
__device__ int    g_idx[B * NPTS * KNN];
__device__ double g_bpart[B][KBLK][27];   // per-block moment partials (no init needed)

// ---------------------------------------------------------------------------
// Branchless stable insertion into sorted-ascending (d, j) list of 20.
// Upper-bound placement (strict <): ties land AFTER equal entries; candidates
// arrive in ascending j -> jax top_k boundary semantics. Idempotent for +INF.
// ---------------------------------------------------------------------------
__device__ __forceinline__ void insert_dj(float (&sd)[KNN], int (&sj)[KNN],
                                          float vd, int vj) {
    bool c[KNN];
#pragma unroll
    for (int k = 0; k < KNN; k++) c[k] = vd < sd[k];
#pragma unroll
    for (int k = KNN - 1; k >= 1; k--) {
        float td = c[k] ? vd : sd[k];
        int   tj = c[k] ? vj : sj[k];
        sd[k] = c[k - 1] ? sd[k - 1] : td;
        sj[k] = c[k - 1] ? sj[k - 1] : tj;
    }
    sd[0] = c[0] ? vd : sd[0];
    sj[0] = c[0] ? vj : sj[0];
}

// ---------------------------------------------------------------------------
// Kernel 1: flat exact KNN + per-block moment partials. 148 blocks total
// (one per SM). Hot loop identical to the validated R12 version: per
// 32-point group, PHASE 1 pure LDS+math, PHASE 2 fused predicated PTX
// (setp.lt + @p st + @p add), one uniform drain-check branch per group.
// Shifted distance d' = d - |q|^2 (monotone per query; set-equivalent).
// ---------------------------------------------------------------------------
__global__ void __launch_bounds__(KTHR) k_knn(const float* __restrict__ x) {
    extern __shared__ char sm[];
    float4* s_pts = (float4*)sm;
    __shared__ double sh[27];

    const int b = blockIdx.y;
    const float* xb = x + b * 3 * NPTS;

    for (int j = threadIdx.x; j < NPTS; j += KTHR) {
        float a0 = xb[j];
        float a1 = xb[NPTS + j];
        float a2 = xb[2 * NPTS + j];
        float sq = fmaf(a0, a0, fmaf(a1, a1, a2 * a2));
        s_pts[j] = make_float4(-2.0f * a0, -2.0f * a1, -2.0f * a2, sq);
    }
    __syncthreads();

    const int tid = threadIdx.x;
    const int iraw = blockIdx.x * KTHR + tid;
    const bool valid = iraw < NPTS;
    const int i = valid ? iraw : (NPTS - 1);
    const float4 ps = s_pts[i];
    const float qx = -0.5f * ps.x, qy = -0.5f * ps.y, qz = -0.5f * ps.z;

    uint32_t sbase;
    asm("{ .reg .u64 t; cvta.to.shared.u64 t, %1; cvt.u32.u64 %0, t; }"
        : "=r"(sbase) : "l"(sm));
    const uint32_t bufA = sbase + (uint32_t)PTS_BYTES +
                          (uint32_t)(tid >> 5) * (uint32_t)WQ_BYTES +
                          (uint32_t)(tid & 31) * 8u;
    const float2* bufP = (const float2*)(sm + PTS_BYTES +
                          (tid >> 5) * WQ_BYTES + (tid & 31) * 8);

    float sd[KNN];
    int   sj[KNN];
#pragma unroll
    for (int k = 0; k < KNN; k++) { sd[k] = INFF; sj[k] = 0; }
    float worst = INFF;
    int   cnt = 0;

#define DRAIN() do {                                                   \
        for (int e = 0; __any_sync(0xffffffffu, e < cnt); e++) {       \
            float2 v = bufP[e * 32];                                   \
            float vd = (e < cnt) ? v.x : INFF;                         \
            insert_dj(sd, sj, vd, __float_as_int(v.y));                \
        }                                                              \
        worst = sd[KNN - 1];                                           \
        cnt = 0;                                                       \
    } while (0)

    for (int j0 = 0; j0 < NPTS; j0 += 32) {
        float dv[32];
#pragma unroll
        for (int u = 0; u < 32; u++) {
            float4 p = s_pts[j0 + u];
            dv[u] = fmaf(qz, p.z, fmaf(qy, p.y, fmaf(qx, p.x, p.w)));
        }
#pragma unroll
        for (int u = 0; u < 32; u++) {
            uint32_t a = bufA + (uint32_t)cnt * 256u;
            asm volatile(
                "{ .reg .pred p; setp.lt.f32 p, %2, %3;"
                "  @p st.shared.v2.b32 [%1], {%4, %5};"
                "  @p add.u32 %0, %0, 1; }"
                : "+r"(cnt)
                : "r"(a), "f"(dv[u]), "f"(worst),
                  "r"(__float_as_int(dv[u])), "r"(j0 + u)
                : "memory");
        }
        // cap proof: post-check cnt <= 15, +32 -> <= 47 < QDEPTH=48
        if (__any_sync(0xffffffffu, cnt >= 16)) DRAIN();
    }
    DRAIN();
#undef DRAIN

    if (valid) {
        int* op = g_idx + (b * NPTS + i) * KNN;
#pragma unroll
        for (int k = 0; k < KNN; k++) op[k] = sj[k];
    }

    // ---------------- fused moment accumulation (per-block partials) -----
    const float nqx = -qx, nqy = -qy, nqz = -qz;
    float sd0 = 0.f, sd1 = 0.f, sd2 = 0.f;
    float s00 = 0.f, s01 = 0.f, s02 = 0.f, s11 = 0.f, s12 = 0.f, s22 = 0.f;
#pragma unroll
    for (int k = 0; k < KNN; k++) {
        float4 p = s_pts[sj[k]];
        float d0 = fmaf(-0.5f, p.x, nqx);
        float d1 = fmaf(-0.5f, p.y, nqy);
        float d2 = fmaf(-0.5f, p.z, nqz);
        sd0 += d0; sd1 += d1; sd2 += d2;
        s00 = fmaf(d0, d0, s00); s01 = fmaf(d0, d1, s01); s02 = fmaf(d0, d2, s02);
        s11 = fmaf(d1, d1, s11); s12 = fmaf(d1, d2, s12); s22 = fmaf(d2, d2, s22);
    }

    float v[27];
    v[0] = KNN * qx; v[1] = KNN * qy; v[2] = KNN * qz;
    v[3] = sd0; v[4] = sd1; v[5] = sd2;
    v[6] = KNN * qx * qx; v[7] = KNN * qx * qy; v[8]  = KNN * qx * qz;
    v[9] = KNN * qy * qy; v[10] = KNN * qy * qz; v[11] = KNN * qz * qz;
    v[12] = qx * sd0; v[13] = qx * sd1; v[14] = qx * sd2;
    v[15] = qy * sd0; v[16] = qy * sd1; v[17] = qy * sd2;
    v[18] = qz * sd0; v[19] = qz * sd1; v[20] = qz * sd2;
    v[21] = s00; v[22] = s01; v[23] = s02; v[24] = s11; v[25] = s12; v[26] = s22;

    const float vm = valid ? 1.0f : 0.0f;
#pragma unroll
    for (int q = 0; q < 27; q++) {
        v[q] *= vm;
#pragma unroll
        for (int off = 16; off > 0; off >>= 1)
            v[q] += __shfl_down_sync(0xffffffffu, v[q], off);
    }

    if (threadIdx.x < 27) sh[threadIdx.x] = 0.0;
    __syncthreads();
    if ((threadIdx.x & 31) == 0) {
#pragma unroll
        for (int q = 0; q < 27; q++) atomicAdd(&sh[q], (double)v[q]);
    }
    __syncthreads();
    if (threadIdx.x < 27)
        g_bpart[b][blockIdx.x][threadIdx.x] = sh[threadIdx.x];
}

// ---------------------------------------------------------------------------
// Kernel 2: reduce block partials -> per-(b,o) mean/rstd (redundantly per
// block, ~0.1us), then conv + tree-max over k + normalize + leaky.
// ---------------------------------------------------------------------------
__global__ void k_out(const float* __restrict__ x, const float* __restrict__ W,
                      float* __restrict__ out) {
    const int b = blockIdx.y;
    const int n = blockIdx.x * blockDim.x + threadIdx.x;

    __shared__ double sG[27];
    __shared__ float sW[OCH * 6];
    __shared__ float sM[OCH];
    __shared__ float sR[OCH];

    if (threadIdx.x < 27) {
        double acc = 0.0;
        for (int blk = 0; blk < KBLK; blk++) acc += g_bpart[b][blk][threadIdx.x];
        sG[threadIdx.x] = acc;
    }
    for (int t = threadIdx.x; t < OCH * 6; t += blockDim.x) sW[t] = W[t];
    __syncthreads();

    if (threadIdx.x < OCH) {
        const int o = threadIdx.x;
        double wa0 = sW[o * 6 + 0], wa1 = sW[o * 6 + 1], wa2 = sW[o * 6 + 2];
        double wb0 = sW[o * 6 + 3], wb1 = sW[o * 6 + 4], wb2 = sW[o * 6 + 5];
        const double NK = (double)NPTS * (double)KNN;

        double mean = (wa0 * sG[0] + wa1 * sG[1] + wa2 * sG[2] +
                       wb0 * sG[3] + wb1 * sG[4] + wb2 * sG[5]) / NK;
        double xx = wa0 * wa0 * sG[6] + 2.0 * wa0 * wa1 * sG[7] + 2.0 * wa0 * wa2 * sG[8] +
                    wa1 * wa1 * sG[9] + 2.0 * wa1 * wa2 * sG[10] + wa2 * wa2 * sG[11];
        double xd = wa0 * (wb0 * sG[12] + wb1 * sG[13] + wb2 * sG[14]) +
                    wa1 * (wb0 * sG[15] + wb1 * sG[16] + wb2 * sG[17]) +
                    wa2 * (wb0 * sG[18] + wb1 * sG[19] + wb2 * sG[20]);
        double dd = wb0 * wb0 * sG[21] + 2.0 * wb0 * wb1 * sG[22] + 2.0 * wb0 * wb2 * sG[23] +
                    wb1 * wb1 * sG[24] + 2.0 * wb1 * wb2 * sG[25] + wb2 * wb2 * sG[26];

        double Ey2 = (xx + 2.0 * xd + dd) / NK;
        double var = Ey2 - mean * mean;
        sM[o] = (float)mean;
        sR[o] = (float)(1.0 / sqrt(var + EPS));
    }
    __syncthreads();

    const float* xb = x + b * 3 * NPTS;
    const float xi0 = xb[n], xi1 = xb[NPTS + n], xi2 = xb[2 * NPTS + n];
    const int* ip = g_idx + (b * NPTS + n) * KNN;

    float d0[KNN], d1[KNN], d2[KNN];
#pragma unroll
    for (int k = 0; k < KNN; k++) {
        int j = ip[k];
        d0[k] = xb[j] - xi0;
        d1[k] = xb[NPTS + j] - xi1;
        d2[k] = xb[2 * NPTS + j] - xi2;
    }

    float* ob = out + (size_t)b * OCH * NPTS + n;
    for (int o = 0; o < OCH; o++) {
        float wa0 = sW[o * 6 + 0], wa1 = sW[o * 6 + 1], wa2 = sW[o * 6 + 2];
        float wb0 = sW[o * 6 + 3], wb1 = sW[o * 6 + 4], wb2 = sW[o * 6 + 5];
        float p = wa0 * xi0;
        p = fmaf(wa1, xi1, p);
        p = fmaf(wa2, xi2, p);
        float y[KNN];
#pragma unroll
        for (int k = 0; k < KNN; k++)
            y[k] = fmaf(wb2, d2[k], fmaf(wb1, d1[k], fmaf(wb0, d0[k], p)));
        // tree max (depth 5) instead of a 20-deep serial chain
#pragma unroll
        for (int k = 0; k < 10; k++) y[k] = fmaxf(y[k], y[k + 10]);
#pragma unroll
        for (int k = 0; k < 5; k++) y[k] = fmaxf(y[k], y[k + 5]);
        y[0] = fmaxf(y[0], y[2]);
        y[1] = fmaxf(y[1], y[3]);
        float m = fmaxf(fmaxf(y[0], y[1]), y[4]);

        float z = (m - sM[o]) * sR[o];
        ob[(size_t)o * NPTS] = (z >= 0.f) ? z : SLOPE * z;
    }
}

// ---------------------------------------------------------------------------
extern "C" void kernel_launch(void* const* d_in, const int* in_sizes, int n_in,
                              void* d_out, int out_size) {
    const float* x = (const float*)d_in[0];   // [B, C, N]
    const float* W = (const float*)d_in[1];   // [O, 2C]
    float* out = (float*)d_out;               // [B, O, N]

    cudaFuncSetAttribute(k_knn, cudaFuncAttributeMaxDynamicSharedMemorySize,
                         SMEM_TOTAL);

    dim3 gknn(KBLK, B);            // 148 blocks total, one per SM
    dim3 gout(NPTS / 256, B);

    k_knn<<<gknn, KTHR, SMEM_TOTAL>>>(x);
    k_out<<<gout, 256>>>(x, W, out);
}